// round 15
// baseline (speedup 1.0000x reference)
#include <cuda_runtime.h>
#include <cuda_bf16.h>
#include <cstdint>

// Problem constants
#define NROWS 32768
#define DIMK  512
#define NCB   16
#define CS    256

// Encoder tiling
#define TM    128
#define TN    256
#define KC    64
#define NCHUNK (DIMK / KC)   // 8
#define TPB   512
#define NSTAGE 4

#define GAP_TAU 0.015f
#define CAP_CB  32768
#define CAND_CAP 262144

__device__ int g_idx[NROWS * NCB];
__device__ int g_cnt_cb[NCB];
__device__ int g_list_cb[NCB * CAP_CB];
__device__ int g_ccnt;
__device__ unsigned int g_cand[CAND_CAP];
__device__ unsigned long long g_best[NROWS * NCB];   // 4 MB
__device__ __nv_bfloat16 g_xbf[NROWS * DIMK];        // 32 MB
__device__ __nv_bfloat16 g_wbf[NCB * CS * DIMK];     // 4 MB

// ---------------- enc smem layout (dynamic) ----------------
#define SM_BIAS 0          // 1024B
#define SM_V1   1024
#define SM_V2   3072
#define SM_I1   5120
#define SM_MX   7168
#define SM_FL   7680
#define SM_BUF  8192
#define ASTR    144        // 64 bf16 = 128B + 16B pad
#define OFF_A   0
#define OFF_B   18432      // 128*144
#define BUFSZ   55296      // + 256*144
#define SMEM_TOTAL (SM_BUF + NSTAGE * BUFSZ)   // 229376 B

__device__ __forceinline__ uint32_t smem_u32(const void* p) {
    uint32_t a;
    asm("{ .reg .u64 t; cvta.to.shared.u64 t, %1; cvt.u32.u64 %0, t; }"
        : "=r"(a) : "l"(p));
    return a;
}
__device__ __forceinline__ void ldm4(uint32_t r[4], uint32_t addr) {
    asm volatile("ldmatrix.sync.aligned.m8n8.x4.shared.b16 {%0,%1,%2,%3}, [%4];"
        : "=r"(r[0]), "=r"(r[1]), "=r"(r[2]), "=r"(r[3]) : "r"(addr));
}
__device__ __forceinline__ void mma_bf16(float d[4], const uint32_t a[4],
                                         uint32_t b0, uint32_t b1) {
    asm volatile("mma.sync.aligned.m16n8k16.row.col.f32.bf16.bf16.f32 "
        "{%0,%1,%2,%3},{%4,%5,%6,%7},{%8,%9},{%0,%1,%2,%3};"
        : "+f"(d[0]), "+f"(d[1]), "+f"(d[2]), "+f"(d[3])
        : "r"(a[0]), "r"(a[1]), "r"(a[2]), "r"(a[3]), "r"(b0), "r"(b1));
}
__device__ __forceinline__ uint32_t cvt2(float a, float b) {
    uint32_t r;
    asm("cvt.rn.bf16x2.f32 %0, %1, %2;" : "=r"(r) : "f"(b), "f"(a));
    return r;
}
__device__ __forceinline__ void cpa16(uint32_t dst, const void* src) {
    asm volatile("cp.async.cg.shared.global [%0], [%1], 16;"
                 :: "r"(dst), "l"(src));
}
// order-preserving float -> u32 (monotone for all finite floats)
__device__ __forceinline__ uint32_t ford(float f) {
    uint32_t u = __float_as_uint(f);
    return (u & 0x80000000u) ? ~u : (u | 0x80000000u);
}

// ---------------------------------------------------------------------------
// Kernel 0: fp32 -> bf16 conversion (8 elems / thread)
// ---------------------------------------------------------------------------
__global__ __launch_bounds__(256)
void cvt_kernel(const float* __restrict__ src, __nv_bfloat16* __restrict__ dst,
                int n8)
{
    int i = blockIdx.x * blockDim.x + threadIdx.x;
    if (i < n8) {
        const float4* s = reinterpret_cast<const float4*>(src) + (size_t)i * 2;
        float4 a = s[0], b = s[1];
        reinterpret_cast<uint4*>(dst)[i] =
            make_uint4(cvt2(a.x, a.y), cvt2(a.z, a.w),
                       cvt2(b.x, b.y), cvt2(b.z, b.w));
    }
}

// ---------------------------------------------------------------------------
// Kernel init: zero counters only (g_best entries are zeroed lazily by enc).
// ---------------------------------------------------------------------------
__global__ void init_kernel()
{
    if (threadIdx.x == 0) g_ccnt = 0;
    if (threadIdx.x < NCB) g_cnt_cb[threadIdx.x] = 0;
}

// ---------------------------------------------------------------------------
// Kernel 1: pure-bf16 GEMM (mma.sync, cp.async 4-stage) + argmax +
//           candidate-column export for near-tie rows.
// grid = (NCB, NROWS/TM), block = 512 (16 warps, 4m x 4n, warp tile 32x64).
// ---------------------------------------------------------------------------
__global__ __launch_bounds__(TPB, 1)
void enc_mma_kernel(const float* __restrict__ bias, int* __restrict__ gidx)
{
    extern __shared__ char smem[];
    const uint32_t sb = smem_u32(smem);
    const int tid  = threadIdx.x;
    const int lane = tid & 31;
    const int wid  = tid >> 5;
    const int wm   = wid >> 2;
    const int wn   = wid & 3;
    const int cb   = blockIdx.x;
    const int row0 = blockIdx.y * TM;

    if (tid < CS)
        *reinterpret_cast<float*>(smem + SM_BIAS + tid * 4) = bias[cb * CS + tid];

    const __nv_bfloat16* xbf = g_xbf + (size_t)row0 * DIMK;
    const __nv_bfloat16* wbf = g_wbf + (size_t)cb * CS * DIMK;

    float acc[2][8][4];
    #pragma unroll
    for (int i = 0; i < 2; ++i)
        #pragma unroll
        for (int j = 0; j < 8; ++j)
            #pragma unroll
            for (int k = 0; k < 4; ++k) acc[i][j][k] = 0.f;

    const int seg = tid & 7;                 // 16B segment (8 bf16)
    uint32_t a_dst[2];  size_t a_src[2];
    uint32_t b_dst[4];  size_t b_src[4];
    #pragma unroll
    for (int e = 0; e < 2; ++e) {
        int row = (tid + 512 * e) >> 3;      // 0..127
        a_dst[e] = OFF_A + row * ASTR + seg * 16;
        a_src[e] = (size_t)row * DIMK + seg * 8;
    }
    #pragma unroll
    for (int e = 0; e < 4; ++e) {
        int row = (tid + 512 * e) >> 3;      // 0..255
        b_dst[e] = OFF_B + row * ASTR + seg * 16;
        b_src[e] = (size_t)row * DIMK + seg * 8;
    }

    #define ISSUE(k0, bufu) do {                                   \
        _Pragma("unroll")                                          \
        for (int e = 0; e < 2; ++e)                                \
            cpa16((bufu) + a_dst[e], xbf + a_src[e] + (k0));       \
        _Pragma("unroll")                                          \
        for (int e = 0; e < 4; ++e)                                \
            cpa16((bufu) + b_dst[e], wbf + b_src[e] + (k0));       \
        asm volatile("cp.async.commit_group;" ::: "memory");       \
    } while (0)

    const uint32_t a_off = (uint32_t)((wm * 32 + (lane & 15)) * ASTR + ((lane >> 4) * 16));
    const uint32_t b_off = (uint32_t)((wn * 64 + (lane & 7) + ((lane & 16) >> 1)) * ASTR
                                      + (((lane >> 3) & 1) * 16));

    // prologue: stage chunks 0,1,2
    ISSUE(0,      sb + SM_BUF + 0 * BUFSZ);
    ISSUE(KC,     sb + SM_BUF + 1 * BUFSZ);
    ISSUE(2 * KC, sb + SM_BUF + 2 * BUFSZ);

    #pragma unroll 1
    for (int c = 0; c < NCHUNK; ++c) {
        // ensure chunk c resident: allow (last_issued - c) groups outstanding
        if (c < NCHUNK - 2)
            asm volatile("cp.async.wait_group 2;" ::: "memory");
        else if (c == NCHUNK - 2)
            asm volatile("cp.async.wait_group 1;" ::: "memory");
        else
            asm volatile("cp.async.wait_group 0;" ::: "memory");
        __syncthreads();

        // stage chunk c+3 into the buffer freed by chunk c-1
        if (c + 3 < NCHUNK)
            ISSUE((c + 3) * KC, sb + SM_BUF + ((c + 3) & 3) * BUFSZ);

        const uint32_t bbase = sb + SM_BUF + (c & 3) * BUFSZ;
        #pragma unroll
        for (int ks = 0; ks < 4; ++ks) {
            uint32_t ah[2][4];
            #pragma unroll
            for (int mi = 0; mi < 2; ++mi)
                ldm4(ah[mi], bbase + OFF_A + a_off + mi * (16 * ASTR) + ks * 32);
            #pragma unroll
            for (int nh = 0; nh < 2; ++nh) {
                uint32_t bh[2][4];
                #pragma unroll
                for (int ng = 0; ng < 2; ++ng)
                    ldm4(bh[ng], bbase + OFF_B + b_off
                         + (uint32_t)((nh * 32 + ng * 16) * ASTR) + ks * 32);
                #pragma unroll
                for (int mi = 0; mi < 2; ++mi) {
                    #pragma unroll
                    for (int nt = 0; nt < 4; ++nt) {
                        const int ng = nt >> 1, rr = (nt & 1) * 2;
                        mma_bf16(acc[mi][nh * 4 + nt], ah[mi],
                                 bh[ng][rr], bh[ng][rr + 1]);
                    }
                }
            }
        }
    }
    #undef ISSUE

    // ---- epilogue: bias + per-warp top-2 over warp's 64 cols ----
    const float* sbias = reinterpret_cast<const float*>(smem + SM_BIAS);
    float* sV1 = reinterpret_cast<float*>(smem + SM_V1);
    float* sV2 = reinterpret_cast<float*>(smem + SM_V2);
    int*   sI1 = reinterpret_cast<int*>(smem + SM_I1);
    float* sMX = reinterpret_cast<float*>(smem + SM_MX);
    int*   sFL = reinterpret_cast<int*>(smem + SM_FL);

    const int g = lane >> 2, q = lane & 3;
    const int colbase = wn * 64;

    float lmax[2][2];   // per-thread pre-merge local max per row-group

    #pragma unroll
    for (int mi = 0; mi < 2; ++mi) {
        #pragma unroll
        for (int h8 = 0; h8 < 2; ++h8) {
            const int row_local = wm * 32 + mi * 16 + h8 * 8 + g;
            float bv = -3.402823466e38f, bv2 = -3.402823466e38f;
            int bc_ = 0;
            #pragma unroll
            for (int nt = 0; nt < 8; ++nt) {
                const int c0 = colbase + nt * 8 + 2 * q;
                float v0 = acc[mi][nt][h8 * 2 + 0] + sbias[c0];
                float v1 = acc[mi][nt][h8 * 2 + 1] + sbias[c0 + 1];
                if (v0 > bv) { bv2 = bv; bv = v0; bc_ = c0; }
                else if (v0 > bv2) bv2 = v0;
                if (v1 > bv) { bv2 = bv; bv = v1; bc_ = c0 + 1; }
                else if (v1 > bv2) bv2 = v1;
            }
            lmax[mi][h8] = bv;   // pre-merge local top (for export guard)
            #pragma unroll
            for (int off = 1; off <= 2; off <<= 1) {
                float ov  = __shfl_xor_sync(0xffffffffu, bv,  off);
                float ov2 = __shfl_xor_sync(0xffffffffu, bv2, off);
                int   oc  = __shfl_xor_sync(0xffffffffu, bc_, off);
                if (ov > bv || (ov == bv && oc < bc_)) {
                    bv2 = fmaxf(bv, ov2); bv = ov; bc_ = oc;
                } else {
                    bv2 = fmaxf(bv2, ov);
                }
            }
            if (q == 0) {
                sV1[row_local * 4 + wn] = bv;
                sV2[row_local * 4 + wn] = bv2;
                sI1[row_local * 4 + wn] = bc_;
            }
        }
    }
    __syncthreads();

    // ---- final cross-warp merge + flag/rowmax broadcast ----
    if (tid < TM) {
        float bv = sV1[tid * 4], bv2 = sV2[tid * 4];
        int bc_ = sI1[tid * 4];
        #pragma unroll
        for (int w = 1; w < 4; ++w) {
            float ov = sV1[tid * 4 + w], ov2 = sV2[tid * 4 + w];
            int oc = sI1[tid * 4 + w];
            if (ov > bv) { bv2 = fmaxf(bv, ov2); bv = ov; bc_ = oc; }
            else bv2 = fmaxf(bv2, ov);
        }
        const int grow = row0 + tid;
        gidx[grow * NCB + cb] = bc_;
        int flg = (bv - bv2 < GAP_TAU) ? 1 : 0;
        sMX[tid] = bv;
        sFL[tid] = flg;
        if (flg) {
            g_best[grow * NCB + cb] = 0ULL;   // lazy init for cand/fix
            int pos = atomicAdd(&g_cnt_cb[cb], 1);
            g_list_cb[cb * CAP_CB + pos] = grow;
        }
    }
    __syncthreads();

    // ---- candidate-column export for flagged rows (guarded by local max) ----
    #pragma unroll
    for (int mi = 0; mi < 2; ++mi) {
        #pragma unroll
        for (int h8 = 0; h8 < 2; ++h8) {
            const int row_local = wm * 32 + mi * 16 + h8 * 8 + g;
            if (!sFL[row_local]) continue;
            const float thr = sMX[row_local] - GAP_TAU;
            if (lmax[mi][h8] < thr) continue;   // none of my 16 cols qualify
            const unsigned base = ((unsigned)(row0 + row_local) << 12)
                                | ((unsigned)cb << 8);
            #pragma unroll
            for (int nt = 0; nt < 8; ++nt) {
                const int c0 = colbase + nt * 8 + 2 * q;
                float v0 = acc[mi][nt][h8 * 2 + 0] + sbias[c0];
                float v1 = acc[mi][nt][h8 * 2 + 1] + sbias[c0 + 1];
                if (v0 >= thr) {
                    int pos = atomicAdd(&g_ccnt, 1);
                    if (pos < CAND_CAP) g_cand[pos] = base | (unsigned)c0;
                }
                if (v1 >= thr) {
                    int pos = atomicAdd(&g_ccnt, 1);
                    if (pos < CAND_CAP) g_cand[pos] = base | (unsigned)(c0 + 1);
                }
            }
        }
    }
}

// ---------------------------------------------------------------------------
// Kernel 2: exact fp32 evaluation of each candidate column.
// One THREAD per candidate: single accumulator, fmas in strictly ascending k
// (float4 loads, component order x,y,z,w) — bitwise the reference-matching
// sequential chain. Publishes via atomicMax(pack).
// ---------------------------------------------------------------------------
__global__ __launch_bounds__(256)
void cand_kernel(const float* __restrict__ x,
                 const float* __restrict__ W,
                 const float* __restrict__ bias)
{
    int total = g_ccnt;
    if (total > CAND_CAP) total = CAND_CAP;
    for (int i = blockIdx.x * blockDim.x + threadIdx.x; i < total;
         i += gridDim.x * blockDim.x) {
        const unsigned p = g_cand[i];
        const int row = p >> 12;
        const int cb  = (p >> 8) & 15;
        const int col = p & 255;
        const float4* xr = reinterpret_cast<const float4*>(x + (size_t)row * DIMK);
        const float4* wr = reinterpret_cast<const float4*>(
            W + (size_t)(cb * CS + col) * DIMK);
        float acc = 0.f;
        #pragma unroll 4
        for (int k4 = 0; k4 < DIMK / 4; ++k4) {
            const float4 xv = __ldg(&xr[k4]);
            const float4 wv = __ldg(&wr[k4]);
            acc = fmaf(xv.x, wv.x, acc);
            acc = fmaf(xv.y, wv.y, acc);
            acc = fmaf(xv.z, wv.z, acc);
            acc = fmaf(xv.w, wv.w, acc);
        }
        const float v = acc + bias[cb * CS + col];
        const unsigned long long pk =
            ((unsigned long long)ford(v) << 32) | (unsigned)(255 - col);
        atomicMax(&g_best[row * NCB + cb], pk);
    }
}

// ---------------------------------------------------------------------------
// Kernel 3: write exact argmax back for flagged rows.
// ---------------------------------------------------------------------------
__global__ __launch_bounds__(256)
void fix_kernel(int* __restrict__ gidx)
{
    const int cb = blockIdx.x;
    int n = g_cnt_cb[cb];
    if (n > CAP_CB) n = CAP_CB;
    for (int i = threadIdx.x; i < n; i += blockDim.x) {
        const int row = g_list_cb[cb * CAP_CB + i];
        const unsigned long long pk = g_best[row * NCB + cb];
        if (pk != 0ULL)
            gidx[row * NCB + cb] = 255 - (int)(pk & 255ULL);
    }
}

// ---------------------------------------------------------------------------
// Kernel 4: decode — gather 16 centers per row, sum, scale.
// ---------------------------------------------------------------------------
__global__ __launch_bounds__(128)
void dec_gather_kernel(const float* __restrict__ centers,
                       const int* __restrict__ gidx,
                       const float* __restrict__ centers_scale,
                       float* __restrict__ out)
{
    __shared__ int   sidx[NCB];
    __shared__ float sscale;
    const int row = blockIdx.x;
    const int tid = threadIdx.x;

    if (tid < NCB) sidx[tid] = gidx[row * NCB + tid];
    if (tid == 0)  sscale = expf(10.0f * centers_scale[0]);
    __syncthreads();

    float4 s = make_float4(0.f, 0.f, 0.f, 0.f);
    #pragma unroll
    for (int c = 0; c < NCB; ++c) {
        const float4* p = reinterpret_cast<const float4*>(
            centers + ((size_t)((c << 8) + sidx[c])) * DIMK);
        float4 v = __ldg(&p[tid]);
        s.x += v.x; s.y += v.y; s.z += v.z; s.w += v.w;
    }
    float sc = sscale;
    s.x *= sc; s.y *= sc; s.z *= sc; s.w *= sc;
    reinterpret_cast<float4*>(out)[(size_t)row * (DIMK / 4) + tid] = s;
}

// ---------------------------------------------------------------------------
extern "C" void kernel_launch(void* const* d_in, const int* in_sizes, int n_in,
                              void* d_out, int out_size)
{
    const float* x       = (const float*)d_in[0];
    const float* W       = (const float*)d_in[1];
    const float* b       = (const float*)d_in[2];
    const float* centers = (const float*)d_in[3];
    const float* cscale  = (const float*)d_in[5];
    float* out           = (float*)d_out;

    int* gidx_ptr = nullptr;
    cudaGetSymbolAddress((void**)&gidx_ptr, g_idx);
    __nv_bfloat16* xbf_ptr = nullptr;
    cudaGetSymbolAddress((void**)&xbf_ptr, g_xbf);
    __nv_bfloat16* wbf_ptr = nullptr;
    cudaGetSymbolAddress((void**)&wbf_ptr, g_wbf);

    cudaFuncSetAttribute(enc_mma_kernel,
                         cudaFuncAttributeMaxDynamicSharedMemorySize, SMEM_TOTAL);

    cvt_kernel<<<(NROWS * DIMK / 8 + 255) / 256, 256>>>(x, xbf_ptr, NROWS * DIMK / 8);
    cvt_kernel<<<(NCB * CS * DIMK / 8 + 255) / 256, 256>>>(W, wbf_ptr, NCB * CS * DIMK / 8);
    init_kernel<<<1, 32>>>();
    dim3 grid1(NCB, NROWS / TM);
    enc_mma_kernel<<<grid1, TPB, SMEM_TOTAL>>>(b, gidx_ptr);
    cand_kernel<<<512, 256>>>(x, W, b);
    fix_kernel<<<NCB, 256>>>(gidx_ptr);
    dec_gather_kernel<<<NROWS, 128>>>(centers, gidx_ptr, cscale, out);
}

// round 16
// speedup vs baseline: 1.0351x; 1.0351x over previous
#include <cuda_runtime.h>
#include <cuda_bf16.h>
#include <cstdint>

// Problem constants
#define NROWS 32768
#define DIMK  512
#define NCB   16
#define CS    256

// Encoder tiling (Round-14 proven config)
#define TM    128
#define TN    256
#define KC    64
#define NCHUNK (DIMK / KC)   // 8
#define TPB   512
#define NSTAGE 3

#define GAP_TAU 0.015f
#define CAP_CB  32768
#define CAND_CAP 262144

__device__ int g_idx[NROWS * NCB];
__device__ int g_cnt_cb[NCB];
__device__ int g_list_cb[NCB * CAP_CB];
__device__ int g_ccnt;
__device__ unsigned int g_cand[CAND_CAP];
__device__ unsigned long long g_best[NROWS * NCB];   // 4 MB (lazy-inited)
__device__ __nv_bfloat16 g_xbf[NROWS * DIMK];        // 32 MB
__device__ __nv_bfloat16 g_wbf[NCB * CS * DIMK];     // 4 MB

#define NX8 (NROWS * DIMK / 8)
#define NW8 (NCB * CS * DIMK / 8)

// ---------------- enc smem layout (dynamic) ----------------
#define SM_BIAS 0          // 1024B
#define SM_V1   1024
#define SM_V2   3072
#define SM_I1   5120
#define SM_MX   7168
#define SM_FL   7680
#define SM_BUF  8192
#define ASTR    144        // 64 bf16 = 128B + 16B pad
#define OFF_A   0
#define OFF_B   18432      // 128*144
#define BUFSZ   55296      // + 256*144
#define SMEM_TOTAL (SM_BUF + NSTAGE * BUFSZ)   // 174080 B

__device__ __forceinline__ uint32_t smem_u32(const void* p) {
    uint32_t a;
    asm("{ .reg .u64 t; cvta.to.shared.u64 t, %1; cvt.u32.u64 %0, t; }"
        : "=r"(a) : "l"(p));
    return a;
}
__device__ __forceinline__ void ldm4(uint32_t r[4], uint32_t addr) {
    asm volatile("ldmatrix.sync.aligned.m8n8.x4.shared.b16 {%0,%1,%2,%3}, [%4];"
        : "=r"(r[0]), "=r"(r[1]), "=r"(r[2]), "=r"(r[3]) : "r"(addr));
}
__device__ __forceinline__ void mma_bf16(float d[4], const uint32_t a[4],
                                         uint32_t b0, uint32_t b1) {
    asm volatile("mma.sync.aligned.m16n8k16.row.col.f32.bf16.bf16.f32 "
        "{%0,%1,%2,%3},{%4,%5,%6,%7},{%8,%9},{%0,%1,%2,%3};"
        : "+f"(d[0]), "+f"(d[1]), "+f"(d[2]), "+f"(d[3])
        : "r"(a[0]), "r"(a[1]), "r"(a[2]), "r"(a[3]), "r"(b0), "r"(b1));
}
__device__ __forceinline__ uint32_t cvt2(float a, float b) {
    uint32_t r;
    asm("cvt.rn.bf16x2.f32 %0, %1, %2;" : "=r"(r) : "f"(b), "f"(a));
    return r;
}
__device__ __forceinline__ void cpa16(uint32_t dst, const void* src) {
    asm volatile("cp.async.cg.shared.global [%0], [%1], 16;"
                 :: "r"(dst), "l"(src));
}
// order-preserving float -> u32 (monotone for all finite floats)
__device__ __forceinline__ uint32_t ford(float f) {
    uint32_t u = __float_as_uint(f);
    return (u & 0x80000000u) ? ~u : (u | 0x80000000u);
}

// ---------------------------------------------------------------------------
// Kernel 0: fused fp32 -> bf16 conversion for x and W + counter init.
// ---------------------------------------------------------------------------
__global__ __launch_bounds__(256)
void cvt_all_kernel(const float* __restrict__ x, const float* __restrict__ W)
{
    int i = blockIdx.x * blockDim.x + threadIdx.x;
    if (i == 0) g_ccnt = 0;
    if (i < NCB) g_cnt_cb[i] = 0;
    const float* src;
    uint4* dst;
    int idx;
    if (i < NX8) {
        src = x; idx = i;
        dst = reinterpret_cast<uint4*>(g_xbf);
    } else if (i < NX8 + NW8) {
        src = W; idx = i - NX8;
        dst = reinterpret_cast<uint4*>(g_wbf);
    } else {
        return;
    }
    const float4* s = reinterpret_cast<const float4*>(src) + (size_t)idx * 2;
    float4 a = s[0], b = s[1];
    dst[idx] = make_uint4(cvt2(a.x, a.y), cvt2(a.z, a.w),
                          cvt2(b.x, b.y), cvt2(b.z, b.w));
}

// ---------------------------------------------------------------------------
// Kernel 1: pure-bf16 GEMM (mma.sync, cp.async 3-stage) + argmax +
//           candidate-column export for near-tie rows.
// grid = (NCB, NROWS/TM), block = 512 (16 warps, 4m x 4n, warp tile 32x64).
// ---------------------------------------------------------------------------
__global__ __launch_bounds__(TPB, 1)
void enc_mma_kernel(const float* __restrict__ bias, int* __restrict__ gidx)
{
    extern __shared__ char smem[];
    const uint32_t sb = smem_u32(smem);
    const int tid  = threadIdx.x;
    const int lane = tid & 31;
    const int wid  = tid >> 5;
    const int wm   = wid >> 2;
    const int wn   = wid & 3;
    const int cb   = blockIdx.x;
    const int row0 = blockIdx.y * TM;

    if (tid < CS)
        *reinterpret_cast<float*>(smem + SM_BIAS + tid * 4) = bias[cb * CS + tid];

    const __nv_bfloat16* xbf = g_xbf + (size_t)row0 * DIMK;
    const __nv_bfloat16* wbf = g_wbf + (size_t)cb * CS * DIMK;

    float acc[2][8][4];
    #pragma unroll
    for (int i = 0; i < 2; ++i)
        #pragma unroll
        for (int j = 0; j < 8; ++j)
            #pragma unroll
            for (int k = 0; k < 4; ++k) acc[i][j][k] = 0.f;

    const int seg = tid & 7;                 // 16B segment (8 bf16)
    uint32_t a_dst[2];  size_t a_src[2];
    uint32_t b_dst[4];  size_t b_src[4];
    #pragma unroll
    for (int e = 0; e < 2; ++e) {
        int row = (tid + 512 * e) >> 3;      // 0..127
        a_dst[e] = OFF_A + row * ASTR + seg * 16;
        a_src[e] = (size_t)row * DIMK + seg * 8;
    }
    #pragma unroll
    for (int e = 0; e < 4; ++e) {
        int row = (tid + 512 * e) >> 3;      // 0..255
        b_dst[e] = OFF_B + row * ASTR + seg * 16;
        b_src[e] = (size_t)row * DIMK + seg * 8;
    }

    #define ISSUE(k0, bufu) do {                                   \
        _Pragma("unroll")                                          \
        for (int e = 0; e < 2; ++e)                                \
            cpa16((bufu) + a_dst[e], xbf + a_src[e] + (k0));       \
        _Pragma("unroll")                                          \
        for (int e = 0; e < 4; ++e)                                \
            cpa16((bufu) + b_dst[e], wbf + b_src[e] + (k0));       \
        asm volatile("cp.async.commit_group;" ::: "memory");       \
    } while (0)

    const uint32_t a_off = (uint32_t)((wm * 32 + (lane & 15)) * ASTR + ((lane >> 4) * 16));
    const uint32_t b_off = (uint32_t)((wn * 64 + (lane & 7) + ((lane & 16) >> 1)) * ASTR
                                      + (((lane >> 3) & 1) * 16));

    ISSUE(0, sb + SM_BUF + 0 * BUFSZ);
    ISSUE(KC, sb + SM_BUF + 1 * BUFSZ);

    int cbuf = 0, ibuf = 2;
    #pragma unroll 1
    for (int c = 0; c < NCHUNK; ++c) {
        if (c + 1 < NCHUNK)
            asm volatile("cp.async.wait_group 1;" ::: "memory");
        else
            asm volatile("cp.async.wait_group 0;" ::: "memory");
        __syncthreads();

        const uint32_t bbase = sb + SM_BUF + cbuf * BUFSZ;
        #pragma unroll
        for (int ks = 0; ks < 4; ++ks) {
            uint32_t ah[2][4];
            #pragma unroll
            for (int mi = 0; mi < 2; ++mi)
                ldm4(ah[mi], bbase + OFF_A + a_off + mi * (16 * ASTR) + ks * 32);
            #pragma unroll
            for (int nh = 0; nh < 2; ++nh) {
                uint32_t bh[2][4];
                #pragma unroll
                for (int ng = 0; ng < 2; ++ng)
                    ldm4(bh[ng], bbase + OFF_B + b_off
                         + (uint32_t)((nh * 32 + ng * 16) * ASTR) + ks * 32);
                #pragma unroll
                for (int mi = 0; mi < 2; ++mi) {
                    #pragma unroll
                    for (int nt = 0; nt < 4; ++nt) {
                        const int ng = nt >> 1, rr = (nt & 1) * 2;
                        mma_bf16(acc[mi][nh * 4 + nt], ah[mi],
                                 bh[ng][rr], bh[ng][rr + 1]);
                    }
                }
            }
        }

        if (c + 2 < NCHUNK) {
            ISSUE((c + 2) * KC, sb + SM_BUF + ibuf * BUFSZ);
            ibuf = (ibuf == NSTAGE - 1) ? 0 : ibuf + 1;
        }
        cbuf = (cbuf == NSTAGE - 1) ? 0 : cbuf + 1;
    }
    #undef ISSUE

    // ---- epilogue: bias + per-warp top-2 over warp's 64 cols ----
    const float* sbias = reinterpret_cast<const float*>(smem + SM_BIAS);
    float* sV1 = reinterpret_cast<float*>(smem + SM_V1);
    float* sV2 = reinterpret_cast<float*>(smem + SM_V2);
    int*   sI1 = reinterpret_cast<int*>(smem + SM_I1);
    float* sMX = reinterpret_cast<float*>(smem + SM_MX);
    int*   sFL = reinterpret_cast<int*>(smem + SM_FL);

    const int g = lane >> 2, q = lane & 3;
    const int colbase = wn * 64;

    float lmax[2][2];   // per-thread pre-merge local max per row-group

    #pragma unroll
    for (int mi = 0; mi < 2; ++mi) {
        #pragma unroll
        for (int h8 = 0; h8 < 2; ++h8) {
            const int row_local = wm * 32 + mi * 16 + h8 * 8 + g;
            float bv = -3.402823466e38f, bv2 = -3.402823466e38f;
            int bc_ = 0;
            #pragma unroll
            for (int nt = 0; nt < 8; ++nt) {
                const int c0 = colbase + nt * 8 + 2 * q;
                float v0 = acc[mi][nt][h8 * 2 + 0] + sbias[c0];
                float v1 = acc[mi][nt][h8 * 2 + 1] + sbias[c0 + 1];
                if (v0 > bv) { bv2 = bv; bv = v0; bc_ = c0; }
                else if (v0 > bv2) bv2 = v0;
                if (v1 > bv) { bv2 = bv; bv = v1; bc_ = c0 + 1; }
                else if (v1 > bv2) bv2 = v1;
            }
            lmax[mi][h8] = bv;
            #pragma unroll
            for (int off = 1; off <= 2; off <<= 1) {
                float ov  = __shfl_xor_sync(0xffffffffu, bv,  off);
                float ov2 = __shfl_xor_sync(0xffffffffu, bv2, off);
                int   oc  = __shfl_xor_sync(0xffffffffu, bc_, off);
                if (ov > bv || (ov == bv && oc < bc_)) {
                    bv2 = fmaxf(bv, ov2); bv = ov; bc_ = oc;
                } else {
                    bv2 = fmaxf(bv2, ov);
                }
            }
            if (q == 0) {
                sV1[row_local * 4 + wn] = bv;
                sV2[row_local * 4 + wn] = bv2;
                sI1[row_local * 4 + wn] = bc_;
            }
        }
    }
    __syncthreads();

    // ---- final cross-warp merge + flag/rowmax broadcast ----
    if (tid < TM) {
        float bv = sV1[tid * 4], bv2 = sV2[tid * 4];
        int bc_ = sI1[tid * 4];
        #pragma unroll
        for (int w = 1; w < 4; ++w) {
            float ov = sV1[tid * 4 + w], ov2 = sV2[tid * 4 + w];
            int oc = sI1[tid * 4 + w];
            if (ov > bv) { bv2 = fmaxf(bv, ov2); bv = ov; bc_ = oc; }
            else bv2 = fmaxf(bv2, ov);
        }
        const int grow = row0 + tid;
        gidx[grow * NCB + cb] = bc_;
        int flg = (bv - bv2 < GAP_TAU) ? 1 : 0;
        sMX[tid] = bv;
        sFL[tid] = flg;
        if (flg) {
            g_best[grow * NCB + cb] = 0ULL;   // lazy init for cand/fix
            int pos = atomicAdd(&g_cnt_cb[cb], 1);
            g_list_cb[cb * CAP_CB + pos] = grow;
        }
    }
    __syncthreads();

    // ---- candidate-column export for flagged rows (guarded by local max) ----
    #pragma unroll
    for (int mi = 0; mi < 2; ++mi) {
        #pragma unroll
        for (int h8 = 0; h8 < 2; ++h8) {
            const int row_local = wm * 32 + mi * 16 + h8 * 8 + g;
            if (!sFL[row_local]) continue;
            const float thr = sMX[row_local] - GAP_TAU;
            if (lmax[mi][h8] < thr) continue;   // none of my 16 cols qualify
            const unsigned base = ((unsigned)(row0 + row_local) << 12)
                                | ((unsigned)cb << 8);
            #pragma unroll
            for (int nt = 0; nt < 8; ++nt) {
                const int c0 = colbase + nt * 8 + 2 * q;
                float v0 = acc[mi][nt][h8 * 2 + 0] + sbias[c0];
                float v1 = acc[mi][nt][h8 * 2 + 1] + sbias[c0 + 1];
                if (v0 >= thr) {
                    int pos = atomicAdd(&g_ccnt, 1);
                    if (pos < CAND_CAP) g_cand[pos] = base | (unsigned)c0;
                }
                if (v1 >= thr) {
                    int pos = atomicAdd(&g_ccnt, 1);
                    if (pos < CAND_CAP) g_cand[pos] = base | (unsigned)(c0 + 1);
                }
            }
        }
    }
}

// ---------------------------------------------------------------------------
// Kernel 2: exact fp32 evaluation of each candidate column.
// One THREAD per candidate: single accumulator, fmas in strictly ascending k
// (float4 loads, component order x,y,z,w) — bitwise identical to the
// reference-matching sequential chain. Publishes via atomicMax(pack).
// ---------------------------------------------------------------------------
__global__ __launch_bounds__(256)
void cand_kernel(const float* __restrict__ x,
                 const float* __restrict__ W,
                 const float* __restrict__ bias)
{
    int total = g_ccnt;
    if (total > CAND_CAP) total = CAND_CAP;
    for (int i = blockIdx.x * blockDim.x + threadIdx.x; i < total;
         i += gridDim.x * blockDim.x) {
        const unsigned p = g_cand[i];
        const int row = p >> 12;
        const int cb  = (p >> 8) & 15;
        const int col = p & 255;
        const float4* xr = reinterpret_cast<const float4*>(x + (size_t)row * DIMK);
        const float4* wr = reinterpret_cast<const float4*>(
            W + (size_t)(cb * CS + col) * DIMK);
        float acc = 0.f;
        #pragma unroll 4
        for (int k4 = 0; k4 < DIMK / 4; ++k4) {
            const float4 xv = __ldg(&xr[k4]);
            const float4 wv = __ldg(&wr[k4]);
            acc = fmaf(xv.x, wv.x, acc);
            acc = fmaf(xv.y, wv.y, acc);
            acc = fmaf(xv.z, wv.z, acc);
            acc = fmaf(xv.w, wv.w, acc);
        }
        const float v = acc + bias[cb * CS + col];
        const unsigned long long pk =
            ((unsigned long long)ford(v) << 32) | (unsigned)(255 - col);
        atomicMax(&g_best[row * NCB + cb], pk);
    }
}

// ---------------------------------------------------------------------------
// Kernel 3: write exact argmax back for flagged rows (grid-strided over cbs).
// ---------------------------------------------------------------------------
__global__ __launch_bounds__(256)
void fix_kernel(int* __restrict__ gidx)
{
    const int cb = blockIdx.x & 15;
    const int sub = blockIdx.x >> 4;      // 4 blocks per cb
    int n = g_cnt_cb[cb];
    if (n > CAP_CB) n = CAP_CB;
    for (int i = sub * 256 + threadIdx.x; i < n; i += 4 * 256) {
        const int row = g_list_cb[cb * CAP_CB + i];
        const unsigned long long pk = g_best[row * NCB + cb];
        if (pk != 0ULL)
            gidx[row * NCB + cb] = 255 - (int)(pk & 255ULL);
    }
}

// ---------------------------------------------------------------------------
// Kernel 4: decode — gather 16 centers per row, sum, scale.
// ---------------------------------------------------------------------------
__global__ __launch_bounds__(128)
void dec_gather_kernel(const float* __restrict__ centers,
                       const int* __restrict__ gidx,
                       const float* __restrict__ centers_scale,
                       float* __restrict__ out)
{
    __shared__ int   sidx[NCB];
    __shared__ float sscale;
    const int row = blockIdx.x;
    const int tid = threadIdx.x;

    if (tid < NCB) sidx[tid] = gidx[row * NCB + tid];
    if (tid == 0)  sscale = expf(10.0f * centers_scale[0]);
    __syncthreads();

    float4 s = make_float4(0.f, 0.f, 0.f, 0.f);
    #pragma unroll
    for (int c = 0; c < NCB; ++c) {
        const float4* p = reinterpret_cast<const float4*>(
            centers + ((size_t)((c << 8) + sidx[c])) * DIMK);
        float4 v = __ldg(&p[tid]);
        s.x += v.x; s.y += v.y; s.z += v.z; s.w += v.w;
    }
    float sc = sscale;
    s.x *= sc; s.y *= sc; s.z *= sc; s.w *= sc;
    reinterpret_cast<float4*>(out)[(size_t)row * (DIMK / 4) + tid] = s;
}

// ---------------------------------------------------------------------------
extern "C" void kernel_launch(void* const* d_in, const int* in_sizes, int n_in,
                              void* d_out, int out_size)
{
    const float* x       = (const float*)d_in[0];
    const float* W       = (const float*)d_in[1];
    const float* b       = (const float*)d_in[2];
    const float* centers = (const float*)d_in[3];
    const float* cscale  = (const float*)d_in[5];
    float* out           = (float*)d_out;

    int* gidx_ptr = nullptr;
    cudaGetSymbolAddress((void**)&gidx_ptr, g_idx);

    cudaFuncSetAttribute(enc_mma_kernel,
                         cudaFuncAttributeMaxDynamicSharedMemorySize, SMEM_TOTAL);

    cvt_all_kernel<<<(NX8 + NW8 + 255) / 256, 256>>>(x, W);
    dim3 grid1(NCB, NROWS / TM);
    enc_mma_kernel<<<grid1, TPB, SMEM_TOTAL>>>(b, gidx_ptr);
    cand_kernel<<<512, 256>>>(x, W, b);
    fix_kernel<<<NCB * 4, 256>>>(gidx_ptr);
    dec_gather_kernel<<<NROWS, 128>>>(centers, gidx_ptr, cscale, out);
}